// round 8
// baseline (speedup 1.0000x reference)
#include <cuda_runtime.h>
#include <cstdint>

// Problem constants
#define Bk 4
#define Ck 256
#define Hk 96
#define Wk 160
#define HWk (Hk * Wk)            // 15360
#define PPk 81

// Tiling: 16x8 pixel tile, 9 warps (one per dy), 4 px/thread, 2 CTAs/SM
#define TW 16
#define TH 8
#define KC 8                     // channels per chunk
#define NCH (Ck / KC)            // 32 chunks
#define NTHREADS 288             // 9 warps

// Shared strides: 48 floats => consecutive rows 16 banks apart; both LDS.128
// phases (2 rows x 4 xq per 8-lane phase) are conflict-free.
#define S0R 48                   // f0 row (16 used)
#define S1R 48                   // f1 halo row (24 used)
#define S0SZ (KC * TH * S0R)     // 3072 floats
#define S1SZ (KC * 16 * S1R)     // 6144 floats
#define BUFSZ (S0SZ + S1SZ)      // 9216 floats
#define SMEM_FLOATS (2 * BUFSZ)  // 18432 floats = 73728 B per CTA

__device__ __forceinline__ void cp_async16(unsigned saddr, const void* g) {
    asm volatile("cp.async.cg.shared.global [%0], [%1], 16;\n" ::"r"(saddr), "l"(g));
}
__device__ __forceinline__ void cp_async8(unsigned saddr, const void* g, int sz) {
    asm volatile("cp.async.ca.shared.global [%0], [%1], 8, %2;\n" ::"r"(saddr), "l"(g), "r"(sz));
}

__global__ void __launch_bounds__(NTHREADS, 2)
corr_kernel(const float* __restrict__ f0, const float* __restrict__ f1,
            float* __restrict__ out) {
    extern __shared__ float smem[];

    const int t    = threadIdx.x;
    const int x0   = blockIdx.x * TW;
    const int y0   = blockIdx.y * TH;
    const int b    = blockIdx.z;

    const int dyw  = t >> 5;                 // 0..8  -> dy = dyw-4
    const int lane = t & 31;
    const int r    = lane >> 2;              // 0..7 tile row
    const int xq   = lane & 3;               // 0..3
    const int xoff = xq * 4;                 // 0..12

    const float* f0b = f0 + (size_t)b * Ck * HWk;
    const float* f1b = f1 + (size_t)b * Ck * HWk;

    float acc[4][9];
#pragma unroll
    for (int p = 0; p < 4; p++)
#pragma unroll
        for (int j = 0; j < 9; j++) acc[p][j] = 0.0f;

    // ---- cooperative chunk prefetch (cp.async, zero-fill halo) ----
    auto prefetch = [&](int c0, int bsel) {
        float* s0 = smem + bsel * BUFSZ;
        float* s1 = s0 + S0SZ;
        // f0 tile: KC x TH x 16 -> 256 float4 transfers (threads 0..255)
        if (t < 256) {
            int c   = t >> 5;             // /32
            int rem = t & 31;
            int row = rem >> 2;
            int col = (rem & 3) << 2;
            const float* g = f0b + ((size_t)(c0 + c) * Hk + (y0 + row)) * Wk + x0 + col;
            unsigned sa = (unsigned)__cvta_generic_to_shared(s0 + (c * TH + row) * S0R + col);
            cp_async16(sa, g);
        }
        // f1 halo: KC x 16 x 24 -> 1536 float2 transfers
#pragma unroll
        for (int i = 0; i < 6; i++) {
            int idx = t + i * NTHREADS;
            if (idx < 1536) {
                int c    = idx / 192;
                int rem  = idx - c * 192;
                int row  = rem / 12;          // 0..15
                int col2 = rem - row * 12;    // 0..11
                int col  = col2 * 2;          // 0..22
                int gy   = y0 - 4 + row;
                int gx   = x0 - 4 + col;      // even; pair uniformly in/out of bounds
                bool ok  = (gy >= 0) && (gy < Hk) && (gx >= 0) && (gx < Wk);
                int gyc  = gy < 0 ? 0 : (gy >= Hk ? Hk - 1 : gy);
                int gxc  = gx < 0 ? 0 : (gx >= Wk ? Wk - 2 : gx);
                const float* g = f1b + ((size_t)(c0 + c) * Hk + gyc) * Wk + gxc;
                unsigned sa = (unsigned)__cvta_generic_to_shared(s1 + (c * 16 + row) * S1R + col);
                cp_async8(sa, g, ok ? 8 : 0);
            }
        }
        asm volatile("cp.async.commit_group;\n" ::: "memory");
    };

    prefetch(0, 0);

#pragma unroll 1
    for (int k = 0; k < NCH; k++) {
        if (k + 1 < NCH) {
            prefetch((k + 1) * KC, (k + 1) & 1);
            asm volatile("cp.async.wait_group 1;\n" ::: "memory");
        } else {
            asm volatile("cp.async.wait_group 0;\n" ::: "memory");
        }
        __syncthreads();

        const float* s0 = smem + (k & 1) * BUFSZ;
        const float* s1 = s0 + S0SZ;

#pragma unroll
        for (int c = 0; c < KC; c++) {
            // 12-float f1 window: halo row r+dyw, cols xoff..xoff+11
            float w[12];
            const float* wp = s1 + (c * 16 + r + dyw) * S1R + xoff;
            *(float4*)&w[0] = *(const float4*)&wp[0];
            *(float4*)&w[4] = *(const float4*)&wp[4];
            *(float4*)&w[8] = *(const float4*)&wp[8];
            // 4 f0 pixels
            float a[4];
            const float* fp = s0 + (c * TH + r) * S0R + xoff;
            *(float4*)&a[0] = *(const float4*)&fp[0];
#pragma unroll
            for (int p = 0; p < 4; p++)
#pragma unroll
                for (int j = 0; j < 9; j++)
                    acc[p][j] = fmaf(a[p], w[p + j], acc[p][j]);
        }
        __syncthreads();
    }

    // ---- epilogue: out[b, dyw*9+j, y0+r, x0+xoff+p] ----
    float* ob = out + (((size_t)b * PPk + dyw * 9) * Hk + (y0 + r)) * Wk + x0 + xoff;
#pragma unroll
    for (int j = 0; j < 9; j++) {
        float* p = ob + (size_t)j * HWk;
        *(float4*)p = make_float4(acc[0][j], acc[1][j], acc[2][j], acc[3][j]);
    }
}

extern "C" void kernel_launch(void* const* d_in, const int* in_sizes, int n_in,
                              void* d_out, int out_size) {
    const float* f0 = (const float*)d_in[0];
    const float* f1 = (const float*)d_in[1];
    float* out      = (float*)d_out;

    const int smem_bytes = SMEM_FLOATS * sizeof(float);  // 73728
    cudaFuncSetAttribute(corr_kernel, cudaFuncAttributeMaxDynamicSharedMemorySize, smem_bytes);

    dim3 grid(Wk / TW, Hk / TH, Bk);  // (10, 12, 4) = 480 blocks
    corr_kernel<<<grid, NTHREADS, smem_bytes>>>(f0, f1, out);
}

// round 13
// speedup vs baseline: 1.2944x; 1.2944x over previous
#include <cuda_runtime.h>
#include <cstdint>

// Problem constants
#define Bk 4
#define Ck 256
#define Hk 96
#define Wk 160
#define HWk (Hk * Wk)            // 15360
#define PPk 81

// Tiling: 32x8 pixel tile, 18 warps = (9 dy) x (2 x-halves), 4 px/thread
#define TW 32
#define TH 8
#define KC 8                     // channels per chunk
#define NCH (Ck / KC)            // 32 chunks
#define NTHREADS 576             // 18 warps
#define NBUF 3                   // triple buffer -> single barrier per chunk

// Shared strides: 48 floats => consecutive rows 16 banks apart; all LDS.128
// read phases (2 rows x 4 xq per 8-lane phase) conflict-free.
#define S0R 48                   // f0 row (32 used)
#define S1R 48                   // f1 halo row (48 used: cols x0-8 .. x0+39)
#define S0SZ (KC * TH * S0R)     // 3072 floats
#define S1SZ (KC * 16 * S1R)     // 6144 floats
#define BUFSZ (S0SZ + S1SZ)      // 9216 floats
#define SMEM_FLOATS (NBUF * BUFSZ)  // 27648 floats = 110592 B

#define F1_CPS (KC * 16 * 12)    // 1536 float4 copies per chunk
#define F0_CPS (KC * TH * 8)     // 512 float4 copies per chunk

__device__ __forceinline__ void cp_async16(unsigned saddr, const void* g) {
    asm volatile("cp.async.cg.shared.global [%0], [%1], 16;\n" ::"r"(saddr), "l"(g));
}
__device__ __forceinline__ void cp_async16z(unsigned saddr, const void* g, int sz) {
    // sz = 16 (copy) or 0 (zero-fill, no gmem read)
    asm volatile("cp.async.cg.shared.global [%0], [%1], 16, %2;\n" ::"r"(saddr), "l"(g), "r"(sz));
}

__global__ void __launch_bounds__(NTHREADS, 1)
corr_kernel(const float* __restrict__ f0, const float* __restrict__ f1,
            float* __restrict__ out) {
    extern __shared__ float smem[];

    const int t    = threadIdx.x;
    const int x0   = blockIdx.x * TW;
    const int y0   = blockIdx.y * TH;
    const int b    = blockIdx.z;

    const int warp = t >> 5;                 // 0..17
    const int lane = t & 31;
    const int dyw  = (warp >= 9) ? warp - 9 : warp;  // 0..8 -> dy = dyw-4
    const int half = (warp >= 9) ? 1 : 0;            // x half
    const int r    = lane >> 2;              // 0..7 tile row
    const int xq   = lane & 3;               // 0..3
    const int xoff = half * 16 + xq * 4;     // 0..28, multiple of 4

    const float* f0b = f0 + (size_t)b * Ck * HWk;
    const float* f1b = f1 + (size_t)b * Ck * HWk;

    // ================= prologue: precompute ALL prefetch addressing =========
    // f0 tile: channel-major idx = c*64 + row*8 + col4 (512 copies), 1/thread
    const bool v0 = (t < F0_CPS);
    const float* g0;
    unsigned sa0;
    {
        int c   = (t >> 6) & 7;
        int pos = t & 63;
        int row = pos >> 3;
        int col = (pos & 7) << 2;
        g0  = f0b + ((size_t)c * Hk + (y0 + row)) * Wk + x0 + col;
        sa0 = (unsigned)__cvta_generic_to_shared(smem + (c * TH + row) * S0R + col);
    }
    // f1 halo: channel-major idx = c*192 + row*12 + col4 (1536 copies), <=3/thread
    // halo cols are x0-8 .. x0+39 (all float4, 16B aligned); OOB -> zero-fill
    const float* g1[3];
    unsigned     sa1[3];
    int          sz1[3];
    bool         v1[3];
#pragma unroll
    for (int i = 0; i < 3; i++) {
        int idx = t + i * NTHREADS;
        v1[i] = (idx < F1_CPS);
        int c    = idx / 192;
        int rem  = idx - c * 192;
        int row  = rem / 12;
        int col  = (rem - row * 12) << 2;
        if (!v1[i]) { c = 0; row = 0; col = 0; }
        int gy = y0 - 4 + row;
        int gx = x0 - 8 + col;
        bool ok = (gy >= 0) && (gy < Hk) && (gx >= 0) && (gx <= Wk - 4);
        int gyc = min(max(gy, 0), Hk - 1);
        int gxc = min(max(gx, 0), Wk - 4);
        g1[i]  = f1b + ((size_t)c * Hk + gyc) * Wk + gxc;
        sa1[i] = (unsigned)__cvta_generic_to_shared(smem + S0SZ + (c * 16 + row) * S1R + col);
        sz1[i] = ok ? 16 : 0;
    }

    // per-chunk prefetch: pure cp.async + pointer advance (no index math)
    auto prefetch = [&](int bsel) {
        unsigned bo = (unsigned)(bsel * (BUFSZ * 4));
        if (v0) cp_async16(sa0 + bo, g0);
#pragma unroll
        for (int i = 0; i < 3; i++)
            if (v1[i]) cp_async16z(sa1[i] + bo, g1[i], sz1[i]);
        asm volatile("cp.async.commit_group;\n" ::: "memory");
        g0 += KC * HWk;
#pragma unroll
        for (int i = 0; i < 3; i++) g1[i] += KC * HWk;
    };

    float acc[4][9];
#pragma unroll
    for (int p = 0; p < 4; p++)
#pragma unroll
        for (int j = 0; j < 9; j++) acc[p][j] = 0.0f;

    prefetch(0);

    int cur = 0;
#pragma unroll 1
    for (int k = 0; k < NCH; k++) {
        int nxt = cur + 1;
        if (nxt == NBUF) nxt = 0;
        if (k + 1 < NCH) {
            prefetch(nxt);
            asm volatile("cp.async.wait_group 1;\n" ::: "memory");
        } else {
            asm volatile("cp.async.wait_group 0;\n" ::: "memory");
        }
        __syncthreads();   // single barrier per chunk (triple buffer makes the
                           // pre-sync prefetch of buf (k+1)%3 race-free)

        const float* s0 = smem + cur * BUFSZ;
        const float* s1 = s0 + S0SZ;

#pragma unroll
        for (int c = 0; c < KC; c++) {
            // 12-float f1 window: halo row r+dyw, halo cols (xoff+4)..(xoff+15)
            float w[12];
            const float* wp = s1 + (c * 16 + r + dyw) * S1R + xoff + 4;
            *(float4*)&w[0] = *(const float4*)&wp[0];
            *(float4*)&w[4] = *(const float4*)&wp[4];
            *(float4*)&w[8] = *(const float4*)&wp[8];
            // 4 f0 pixels
            float a[4];
            const float* fp = s0 + (c * TH + r) * S0R + xoff;
            *(float4*)&a[0] = *(const float4*)&fp[0];
#pragma unroll
            for (int p = 0; p < 4; p++)
#pragma unroll
                for (int j = 0; j < 9; j++)
                    acc[p][j] = fmaf(a[p], w[p + j], acc[p][j]);
        }
        cur = nxt;
    }

    // ---- epilogue: out[b, dyw*9+j, y0+r, x0+xoff+p] ----
    float* ob = out + (((size_t)b * PPk + dyw * 9) * Hk + (y0 + r)) * Wk + x0 + xoff;
#pragma unroll
    for (int j = 0; j < 9; j++) {
        float* p = ob + (size_t)j * HWk;
        *(float4*)p = make_float4(acc[0][j], acc[1][j], acc[2][j], acc[3][j]);
    }
}

extern "C" void kernel_launch(void* const* d_in, const int* in_sizes, int n_in,
                              void* d_out, int out_size) {
    const float* f0 = (const float*)d_in[0];
    const float* f1 = (const float*)d_in[1];
    float* out      = (float*)d_out;

    const int smem_bytes = SMEM_FLOATS * sizeof(float);  // 110592
    cudaFuncSetAttribute(corr_kernel, cudaFuncAttributeMaxDynamicSharedMemorySize, smem_bytes);

    dim3 grid(Wk / TW, Hk / TH, Bk);  // (5, 12, 4) = 240 blocks
    corr_kernel<<<grid, NTHREADS, smem_bytes>>>(f0, f1, out);
}